// round 2
// baseline (speedup 1.0000x reference)
#include <cuda_runtime.h>
#include <stdint.h>
#include <math.h>

// Problem dims (fixed by the dataset)
#define IN_DIM   2048
#define OUT_DIM  2048
#define BATCH    4096
#define GRID_SZ  8
#define LN_EPS   1e-5f

// GEMM config: out[b][o] = sum_k A[b][k] * W[o][k mod 4096]
//   A = [ tf32(xn) | tf32(S) | tf32(xn - tf32(xn)) | tf32(S - tf32(S)) ]  (tf32x2 on A)
//   W = [ tf32(scale_base) | tf32(Wd) ]
#define KDIM 8192
#define WK   4096

#define BM 128
#define BN 128
#define BK 16
#define LDA 20   // padded smem row (floats); conflict-free for mma frag loads

// Scratch (allocation-free rule: __device__ globals)
__device__ float g_A[(size_t)BATCH * KDIM];    // 128 MB
__device__ float g_W[(size_t)OUT_DIM * WK];    //  32 MB

__device__ __forceinline__ float tf32r(float x) {
    uint32_t u;
    asm("cvt.rna.tf32.f32 %0, %1;" : "=r"(u) : "f"(x));
    return __uint_as_float(u);
}

// ---------------------------------------------------------------------------
// Kernel 1: Wd = sum_g spline_weight[o][i][g];  W = [tf32(sb) | tf32(Wd)]
// ---------------------------------------------------------------------------
__global__ __launch_bounds__(256)
void prep_w_kernel(const float* __restrict__ sw, const float* __restrict__ sb) {
    int idx = blockIdx.x * 256 + threadIdx.x;          // 0 .. OUT*IN-1
    int o = idx >> 11;                                 // / IN_DIM
    int i = idx & (IN_DIM - 1);
    const float4* p = (const float4*)(sw + (size_t)idx * GRID_SZ);
    float4 v0 = p[0], v1 = p[1];
    float s = ((v0.x + v0.y) + (v0.z + v0.w)) + ((v1.x + v1.y) + (v1.z + v1.w));
    g_W[(size_t)o * WK + i]          = tf32r(__ldg(sb + idx));
    g_W[(size_t)o * WK + IN_DIM + i] = tf32r(s);
}

// ---------------------------------------------------------------------------
// Kernel 2: fused LayerNorm + RBF basis sum, hi/lo tf32 split into g_A
// One block (256 thr) per batch row.
// ---------------------------------------------------------------------------
__global__ __launch_bounds__(256)
void ln_basis_kernel(const float* __restrict__ x, const float* __restrict__ lnw,
                     const float* __restrict__ lnb, const float* __restrict__ beta_p,
                     const float* __restrict__ grid) {
    const int b = blockIdx.x;
    const int t = threadIdx.x;
    const int lane = t & 31, warp = t >> 5;

    const float4* xr = (const float4*)(x + (size_t)b * IN_DIM);
    float4 xv[2];
    float s = 0.f, ss = 0.f;
#pragma unroll
    for (int j = 0; j < 2; j++) {
        xv[j] = xr[t + 256 * j];
        s  += (xv[j].x + xv[j].y) + (xv[j].z + xv[j].w);
        ss += (xv[j].x * xv[j].x + xv[j].y * xv[j].y)
            + (xv[j].z * xv[j].z + xv[j].w * xv[j].w);
    }
#pragma unroll
    for (int o = 16; o; o >>= 1) {
        s  += __shfl_xor_sync(0xffffffffu, s, o);
        ss += __shfl_xor_sync(0xffffffffu, ss, o);
    }
    __shared__ float red[2][8];
    if (lane == 0) { red[0][warp] = s; red[1][warp] = ss; }
    __syncthreads();
    float ts = 0.f, tss = 0.f;
#pragma unroll
    for (int w = 0; w < 8; w++) { ts += red[0][w]; tss += red[1][w]; }

    const float inv  = 1.0f / IN_DIM;
    const float mean = ts * inv;
    const float var  = tss * inv - mean * mean;
    const float rstd = rsqrtf(var + LN_EPS);
    const float beta = fminf(fmaxf(__ldg(beta_p), 0.5f), 6.0f);

    float gr[8];
#pragma unroll
    for (int g = 0; g < 8; g++) gr[g] = __ldg(grid + g);

    float* Ar = g_A + (size_t)b * KDIM;
#pragma unroll
    for (int j = 0; j < 2; j++) {
        const int c4 = t + 256 * j;
        float4 wv = ((const float4*)lnw)[c4];
        float4 bv = ((const float4*)lnb)[c4];
        float xs[4] = { xv[j].x, xv[j].y, xv[j].z, xv[j].w };
        float ws[4] = { wv.x, wv.y, wv.z, wv.w };
        float bs[4] = { bv.x, bv.y, bv.z, bv.w };
        float xh[4], xl[4], Sh[4], Sl[4];
#pragma unroll
        for (int c = 0; c < 4; c++) {
            float xn = (xs[c] - mean) * rstd * ws[c] + bs[c];
            float S = 0.f;
#pragma unroll
            for (int g = 0; g < 8; g++) {
                float d = xn - gr[g];
                S += __expf(-beta * d * d);
            }
            xh[c] = tf32r(xn); xl[c] = tf32r(xn - xh[c]);   // residual exact in fp32
            Sh[c] = tf32r(S);  Sl[c] = tf32r(S - Sh[c]);
        }
        ((float4*)(Ar           ))[c4] = make_float4(xh[0], xh[1], xh[2], xh[3]);
        ((float4*)(Ar +   IN_DIM))[c4] = make_float4(Sh[0], Sh[1], Sh[2], Sh[3]);
        ((float4*)(Ar + 2*IN_DIM))[c4] = make_float4(xl[0], xl[1], xl[2], xl[3]);
        ((float4*)(Ar + 3*IN_DIM))[c4] = make_float4(Sl[0], Sl[1], Sl[2], Sl[3]);
    }
}

// ---------------------------------------------------------------------------
// Kernel 3: GEMM  out[b][o] = sum_k A[b][k] * W[o][k & (WK-1)] + bias[o]
// 128x128x16 tiles, mma.sync.m16n8k8 tf32, cp.async 2-stage pipeline.
// 8 warps: 4 (m) x 2 (n); warp tile 32x64.
// ---------------------------------------------------------------------------
__global__ __launch_bounds__(256, 2)
void gemm_kernel(float* __restrict__ out, const float* __restrict__ bias) {
    __shared__ float As[2][BM * LDA];
    __shared__ float Bs[2][BN * LDA];

    const int tid  = threadIdx.x;
    const int bm0  = blockIdx.y * BM;
    const int bn0  = blockIdx.x * BN;
    const int warp = tid >> 5, lane = tid & 31;
    const int wm = (warp & 3) << 5;   // 0,32,64,96
    const int wn = (warp >> 2) << 6;  // 0,64
    const int lr = lane >> 2;         // 0..7
    const int lc = lane & 3;          // 0..3

    float acc[2][8][4];
#pragma unroll
    for (int i = 0; i < 2; i++)
#pragma unroll
        for (int j = 0; j < 8; j++)
#pragma unroll
            for (int k = 0; k < 4; k++) acc[i][j][k] = 0.f;

    // per-thread tile-load coords: 512 float4 per matrix, 2 per thread
    const int l_row0 = tid >> 2;                 // rows 0..63
    const int l_row1 = (tid + 256) >> 2;         // rows 64..127
    const int l_c4   = (tid & 3) << 2;           // float col 0,4,8,12

    const float* Abase = g_A + (size_t)bm0 * KDIM;
    const float* Bbase = g_W + (size_t)bn0 * WK;

    auto issue_tile = [&](int buf, int kt) {
        const int ka = kt * BK;
        const int kw = ka & (WK - 1);
        {
            uint32_t d0 = (uint32_t)__cvta_generic_to_shared(&As[buf][l_row0 * LDA + l_c4]);
            uint32_t d1 = (uint32_t)__cvta_generic_to_shared(&As[buf][l_row1 * LDA + l_c4]);
            const float* s0 = Abase + (size_t)l_row0 * KDIM + ka + l_c4;
            const float* s1 = Abase + (size_t)l_row1 * KDIM + ka + l_c4;
            asm volatile("cp.async.cg.shared.global [%0], [%1], 16;\n" :: "r"(d0), "l"(s0));
            asm volatile("cp.async.cg.shared.global [%0], [%1], 16;\n" :: "r"(d1), "l"(s1));
        }
        {
            uint32_t d0 = (uint32_t)__cvta_generic_to_shared(&Bs[buf][l_row0 * LDA + l_c4]);
            uint32_t d1 = (uint32_t)__cvta_generic_to_shared(&Bs[buf][l_row1 * LDA + l_c4]);
            const float* s0 = Bbase + (size_t)l_row0 * WK + kw + l_c4;
            const float* s1 = Bbase + (size_t)l_row1 * WK + kw + l_c4;
            asm volatile("cp.async.cg.shared.global [%0], [%1], 16;\n" :: "r"(d0), "l"(s0));
            asm volatile("cp.async.cg.shared.global [%0], [%1], 16;\n" :: "r"(d1), "l"(s1));
        }
    };

    const int NT = KDIM / BK;   // 512

    issue_tile(0, 0);
    asm volatile("cp.async.commit_group;\n" ::);

    for (int kt = 0; kt < NT; kt++) {
        const int cur = kt & 1;
        if (kt + 1 < NT) {
            issue_tile(cur ^ 1, kt + 1);
            asm volatile("cp.async.commit_group;\n" ::);
            asm volatile("cp.async.wait_group 1;\n" ::);
        } else {
            asm volatile("cp.async.wait_group 0;\n" ::);
        }
        __syncthreads();

        const float* Ab = As[cur];
        const float* Bb = Bs[cur];
#pragma unroll
        for (int kk = 0; kk < 2; kk++) {
            const int kc = kk * 8 + lc;
            uint32_t a[2][4];
#pragma unroll
            for (int tm = 0; tm < 2; tm++) {
                const int r = wm + tm * 16 + lr;
                a[tm][0] = __float_as_uint(Ab[r * LDA + kc]);
                a[tm][1] = __float_as_uint(Ab[(r + 8) * LDA + kc]);
                a[tm][2] = __float_as_uint(Ab[r * LDA + kc + 4]);
                a[tm][3] = __float_as_uint(Ab[(r + 8) * LDA + kc + 4]);
            }
#pragma unroll
            for (int tn = 0; tn < 8; tn++) {
                const int n = wn + tn * 8 + lr;
                uint32_t b0 = __float_as_uint(Bb[n * LDA + kc]);
                uint32_t b1 = __float_as_uint(Bb[n * LDA + kc + 4]);
#pragma unroll
                for (int tm = 0; tm < 2; tm++) {
                    asm volatile(
                        "mma.sync.aligned.m16n8k8.row.col.f32.tf32.tf32.f32 "
                        "{%0,%1,%2,%3}, {%4,%5,%6,%7}, {%8,%9}, {%0,%1,%2,%3};\n"
                        : "+f"(acc[tm][tn][0]), "+f"(acc[tm][tn][1]),
                          "+f"(acc[tm][tn][2]), "+f"(acc[tm][tn][3])
                        : "r"(a[tm][0]), "r"(a[tm][1]), "r"(a[tm][2]), "r"(a[tm][3]),
                          "r"(b0), "r"(b1));
                }
            }
        }
        __syncthreads();
    }

    // Epilogue: add bias, store
#pragma unroll
    for (int tm = 0; tm < 2; tm++) {
        const int r0 = bm0 + wm + tm * 16 + lr;
#pragma unroll
        for (int tn = 0; tn < 8; tn++) {
            const int c0 = bn0 + wn + tn * 8 + 2 * lc;
            const float bb0 = __ldg(bias + c0);
            const float bb1 = __ldg(bias + c0 + 1);
            float2 v;
            v.x = acc[tm][tn][0] + bb0;
            v.y = acc[tm][tn][1] + bb1;
            *(float2*)(out + (size_t)r0 * OUT_DIM + c0) = v;
            v.x = acc[tm][tn][2] + bb0;
            v.y = acc[tm][tn][3] + bb1;
            *(float2*)(out + (size_t)(r0 + 8) * OUT_DIM + c0) = v;
        }
    }
}

// ---------------------------------------------------------------------------
extern "C" void kernel_launch(void* const* d_in, const int* in_sizes, int n_in,
                              void* d_out, int out_size) {
    const float* x    = (const float*)d_in[0];
    const float* lnw  = (const float*)d_in[1];
    const float* lnb  = (const float*)d_in[2];
    const float* sw   = (const float*)d_in[3];
    const float* sb   = (const float*)d_in[4];
    const float* bias = (const float*)d_in[5];
    const float* beta = (const float*)d_in[6];
    const float* grid = (const float*)d_in[7];
    float* out = (float*)d_out;

    prep_w_kernel<<<(OUT_DIM * IN_DIM) / 256, 256>>>(sw, sb);
    ln_basis_kernel<<<BATCH, 256>>>(x, lnw, lnb, beta, grid);
    gemm_kernel<<<dim3(OUT_DIM / BN, BATCH / BM), 256>>>(out, bias);
}

// round 4
// speedup vs baseline: 2.9264x; 2.9264x over previous
#include <cuda_runtime.h>
#include <cuda.h>
#include <cuda_bf16.h>
#include <stdint.h>
#include <math.h>

// Problem dims
#define IN_DIM   2048
#define OUT_DIM  2048
#define BATCH    4096
#define GRID_SZ  8
#define LN_EPS   1e-5f

// bf16 3-segment split GEMM:
//   A phys [BATCH][8192] bf16: cols [0,4096)=Ah=[bf16(xn)|bf16(S)], [4096,8192)=Al
//   W phys [OUT][8192]  bf16: cols [0,4096)=Wh=[bf16(sb)|bf16(Wd)], [4096,8192)=Wl
//   K_virt=12288: seg0 Ah*Wh, seg1 Ah*Wl, seg2 Al*Wh (AlWl ~4e-6 rel, dropped)
#define KPHYS  8192
#define KVIRT  12288
#define BM     128
#define BN     128
#define BK     64
#define STAGES 3
#define NKIT   (KVIRT / BK)   // 192

// Scratch (__device__ globals: allocation-free rule)
__device__ __nv_bfloat16 g_A[(size_t)BATCH   * KPHYS];  // 64 MB
__device__ __nv_bfloat16 g_W[(size_t)OUT_DIM * KPHYS];  // 32 MB

// smem layout for GEMM
#define SM_MBAR     0
#define SM_A0       1024
#define TILE_BYTES  (BM * BK * 2)        // 16384
#define STAGE_BYTES (2 * TILE_BYTES)     // 32768 (A then B)
#define SM_TOT      (1024 + STAGES * STAGE_BYTES)  // 99328

// ---------------------------------------------------------------------------
// helpers
// ---------------------------------------------------------------------------
__device__ __forceinline__ uint32_t smem_u32(const void* p) {
    uint32_t a;
    asm("{ .reg .u64 t; cvta.to.shared.u64 t, %1; cvt.u32.u64 %0, t; }" : "=r"(a) : "l"(p));
    return a;
}
__device__ __forceinline__ void mbar_init(uint32_t addr, uint32_t cnt) {
    asm volatile("mbarrier.init.shared.b64 [%0], %1;" :: "r"(addr), "r"(cnt) : "memory");
}
__device__ __forceinline__ void mbar_wait(uint32_t addr, uint32_t parity) {
    uint32_t done;
    asm volatile("{\n\t.reg .pred p;\n\t"
                 "mbarrier.try_wait.parity.acquire.cta.shared::cta.b64 p, [%1], %2;\n\t"
                 "selp.b32 %0, 1, 0, p;\n\t}"
                 : "=r"(done) : "r"(addr), "r"(parity) : "memory");
    if (!done) {
        asm volatile("{\n\t.reg .pred P1;\n\t"
                     "W0_%=:\n\t"
                     "mbarrier.try_wait.parity.acquire.cta.shared::cta.b64 P1, [%0], %1, 0x989680;\n\t"
                     "@P1 bra.uni WD_%=;\n\t"
                     "bra.uni W0_%=;\n\t"
                     "WD_%=:\n\t}" :: "r"(addr), "r"(parity) : "memory");
    }
}
__device__ __forceinline__ uint32_t sw128(uint32_t off) {
    return off ^ ((off >> 3) & 0x70);
}

// ---------------------------------------------------------------------------
// Kernel 1: W prep — hi/lo bf16 split of [scale_base | sum_g spline_weight]
// ---------------------------------------------------------------------------
__global__ __launch_bounds__(256)
void prep_w_kernel(const float* __restrict__ sw, const float* __restrict__ sb) {
    int idx = blockIdx.x * 256 + threadIdx.x;   // 0 .. OUT*IN-1
    int o = idx >> 11;
    int i = idx & (IN_DIM - 1);
    const float4* p = (const float4*)(sw + (size_t)idx * GRID_SZ);
    float4 v0 = p[0], v1 = p[1];
    float wd = ((v0.x + v0.y) + (v0.z + v0.w)) + ((v1.x + v1.y) + (v1.z + v1.w));
    float s  = __ldg(sb + idx);

    __nv_bfloat16 sh = __float2bfloat16_rn(s);
    __nv_bfloat16 sl = __float2bfloat16_rn(s - __bfloat162float(sh));
    __nv_bfloat16 wh = __float2bfloat16_rn(wd);
    __nv_bfloat16 wl = __float2bfloat16_rn(wd - __bfloat162float(wh));

    __nv_bfloat16* r = g_W + (size_t)o * KPHYS;
    r[i]                 = sh;   // Wh: sb
    r[IN_DIM + i]        = wh;   // Wh: Wd
    r[4096 + i]          = sl;   // Wl: sb
    r[4096 + IN_DIM + i] = wl;   // Wl: Wd
}

// ---------------------------------------------------------------------------
// Kernel 2: LayerNorm + RBF sum, hi/lo bf16 split. One block per batch row.
// ---------------------------------------------------------------------------
__global__ __launch_bounds__(256)
void ln_basis_kernel(const float* __restrict__ x, const float* __restrict__ lnw,
                     const float* __restrict__ lnb, const float* __restrict__ beta_p,
                     const float* __restrict__ grid) {
    const int b = blockIdx.x;
    const int t = threadIdx.x;
    const int lane = t & 31, warp = t >> 5;

    const float4* xr = (const float4*)(x + (size_t)b * IN_DIM);
    float4 xv[2];
    float s = 0.f, ss = 0.f;
#pragma unroll
    for (int j = 0; j < 2; j++) {
        xv[j] = xr[t + 256 * j];
        s  += (xv[j].x + xv[j].y) + (xv[j].z + xv[j].w);
        ss += (xv[j].x * xv[j].x + xv[j].y * xv[j].y)
            + (xv[j].z * xv[j].z + xv[j].w * xv[j].w);
    }
#pragma unroll
    for (int o = 16; o; o >>= 1) {
        s  += __shfl_xor_sync(0xffffffffu, s, o);
        ss += __shfl_xor_sync(0xffffffffu, ss, o);
    }
    __shared__ float red[2][8];
    if (lane == 0) { red[0][warp] = s; red[1][warp] = ss; }
    __syncthreads();
    float ts = 0.f, tss = 0.f;
#pragma unroll
    for (int w = 0; w < 8; w++) { ts += red[0][w]; tss += red[1][w]; }

    const float inv  = 1.0f / IN_DIM;
    const float mean = ts * inv;
    const float var  = tss * inv - mean * mean;
    const float rstd = rsqrtf(var + LN_EPS);
    const float beta = fminf(fmaxf(__ldg(beta_p), 0.5f), 6.0f);

    float gr[8];
#pragma unroll
    for (int g = 0; g < 8; g++) gr[g] = __ldg(grid + g);

    __nv_bfloat16* Ar = g_A + (size_t)b * KPHYS;
#pragma unroll
    for (int j = 0; j < 2; j++) {
        const int c4 = t + 256 * j;
        float4 wv = ((const float4*)lnw)[c4];
        float4 bv = ((const float4*)lnb)[c4];
        float xs[4] = { xv[j].x, xv[j].y, xv[j].z, xv[j].w };
        float ws[4] = { wv.x, wv.y, wv.z, wv.w };
        float bs[4] = { bv.x, bv.y, bv.z, bv.w };
        __nv_bfloat16 xh[4], xl[4], Sh[4], Sl[4];
#pragma unroll
        for (int c = 0; c < 4; c++) {
            float xn = (xs[c] - mean) * rstd * ws[c] + bs[c];
            float S = 0.f;
#pragma unroll
            for (int g = 0; g < 8; g++) {
                float d = xn - gr[g];
                S += __expf(-beta * d * d);
            }
            xh[c] = __float2bfloat16_rn(xn);
            xl[c] = __float2bfloat16_rn(xn - __bfloat162float(xh[c]));
            Sh[c] = __float2bfloat16_rn(S);
            Sl[c] = __float2bfloat16_rn(S - __bfloat162float(Sh[c]));
        }
        const int col = 4 * c4;
        *(__nv_bfloat162*)(Ar + col)            = __nv_bfloat162(xh[0], xh[1]);
        *(__nv_bfloat162*)(Ar + col + 2)        = __nv_bfloat162(xh[2], xh[3]);
        *(__nv_bfloat162*)(Ar + 2048 + col)     = __nv_bfloat162(Sh[0], Sh[1]);
        *(__nv_bfloat162*)(Ar + 2048 + col + 2) = __nv_bfloat162(Sh[2], Sh[3]);
        *(__nv_bfloat162*)(Ar + 4096 + col)     = __nv_bfloat162(xl[0], xl[1]);
        *(__nv_bfloat162*)(Ar + 4096 + col + 2) = __nv_bfloat162(xl[2], xl[3]);
        *(__nv_bfloat162*)(Ar + 6144 + col)     = __nv_bfloat162(Sl[0], Sl[1]);
        *(__nv_bfloat162*)(Ar + 6144 + col + 2) = __nv_bfloat162(Sl[2], Sl[3]);
    }
}

// ---------------------------------------------------------------------------
// Kernel 3: GEMM via mma.sync bf16 + TMA(SW128) 3-stage ring.
// 128x128 tile, 8 warps (2m x 4n), warp tile 64x32.
// ---------------------------------------------------------------------------
__global__ __launch_bounds__(256, 2)
void gemm_kernel(float* __restrict__ out, const float* __restrict__ bias,
                 const __grid_constant__ CUtensorMap ta,
                 const __grid_constant__ CUtensorMap tb) {
    extern __shared__ char smem[];
    const uint32_t sb = smem_u32(smem);
    const int tid  = threadIdx.x;
    const int warp = tid >> 5, lane = tid & 31;
    const int bm0  = blockIdx.y * BM;
    const int bn0  = blockIdx.x * BN;
    const int wm   = (warp & 1) * 64;
    const int wn   = (warp >> 1) * 32;

    if (tid == 0) {
#pragma unroll
        for (int s = 0; s < STAGES; s++) mbar_init(sb + SM_MBAR + 8 * s, 1);
    }
    __syncthreads();

    auto issue = [&](int s) {
        const int kv = s * BK;
        const int ka = kv < 4096 ? kv : kv - 4096;
        const int kw = kv < 8192 ? kv : kv - 8192;
        const int buf = s % STAGES;
        const uint32_t mb = sb + SM_MBAR + 8 * buf;
        const uint32_t da = sb + SM_A0 + buf * STAGE_BYTES;
        const uint32_t db = da + TILE_BYTES;
        asm volatile("mbarrier.arrive.expect_tx.shared.b64 _, [%0], %1;"
                     :: "r"(mb), "r"((uint32_t)STAGE_BYTES) : "memory");
        asm volatile("cp.async.bulk.tensor.2d.shared::cta.global.tile.mbarrier::complete_tx::bytes"
                     " [%0], [%1, {%2, %3}], [%4];"
                     :: "r"(da), "l"(&ta), "r"(ka), "r"(bm0), "r"(mb) : "memory");
        asm volatile("cp.async.bulk.tensor.2d.shared::cta.global.tile.mbarrier::complete_tx::bytes"
                     " [%0], [%1, {%2, %3}], [%4];"
                     :: "r"(db), "l"(&tb), "r"(kw), "r"(bn0), "r"(mb) : "memory");
    };

    if (tid == 0) { issue(0); issue(1); issue(2); }

    float acc[4][4][4];
#pragma unroll
    for (int a = 0; a < 4; a++)
#pragma unroll
        for (int b = 0; b < 4; b++)
#pragma unroll
            for (int c = 0; c < 4; c++) acc[a][b][c] = 0.f;

    for (int s = 0; s < NKIT; s++) {
        const int buf = s % STAGES;
        mbar_wait(sb + SM_MBAR + 8 * buf, (s / STAGES) & 1);
        const uint32_t da = sb + SM_A0 + buf * STAGE_BYTES;
        const uint32_t db = da + TILE_BYTES;

#pragma unroll
        for (int kk = 0; kk < 4; kk++) {
            // A frags: 4 m16-tiles; lanes0-15: rows, k0-7 chunk; lanes16-31: k8-15
            uint32_t A[4][4];
#pragma unroll
            for (int mt = 0; mt < 4; mt++) {
                const uint32_t row = (uint32_t)(wm + mt * 16 + (lane & 15));
                const uint32_t ch  = (uint32_t)(kk * 2 + (lane >> 4));
                const uint32_t ad  = da + sw128(row * 128 + ch * 16);
                asm volatile("ldmatrix.sync.aligned.m8n8.x4.shared.b16 {%0,%1,%2,%3}, [%4];"
                             : "=r"(A[mt][0]), "=r"(A[mt][1]), "=r"(A[mt][2]), "=r"(A[mt][3])
                             : "r"(ad));
            }
            // B frags: same pattern (W rows are n, k-contiguous -> non-trans ldmatrix)
            // x4 matrices: m0=(n0-7,k0-7) m1=(n8-15,k0-7) m2=(n0-7,k8-15) m3=(n8-15,k8-15)
            uint32_t B[2][4];
#pragma unroll
            for (int nt = 0; nt < 2; nt++) {
                const uint32_t row = (uint32_t)(wn + nt * 16 + (lane & 15));
                const uint32_t ch  = (uint32_t)(kk * 2 + (lane >> 4));
                const uint32_t ad  = db + sw128(row * 128 + ch * 16);
                asm volatile("ldmatrix.sync.aligned.m8n8.x4.shared.b16 {%0,%1,%2,%3}, [%4];"
                             : "=r"(B[nt][0]), "=r"(B[nt][1]), "=r"(B[nt][2]), "=r"(B[nt][3])
                             : "r"(ad));
            }
#pragma unroll
            for (int mt = 0; mt < 4; mt++) {
#pragma unroll
                for (int j = 0; j < 4; j++) {
                    const int nt = j >> 1, h = j & 1;  // n8 tile j: regs {B[nt][h], B[nt][h+2]}
                    asm volatile(
                        "mma.sync.aligned.m16n8k16.row.col.f32.bf16.bf16.f32 "
                        "{%0,%1,%2,%3}, {%4,%5,%6,%7}, {%8,%9}, {%0,%1,%2,%3};"
                        : "+f"(acc[mt][j][0]), "+f"(acc[mt][j][1]),
                          "+f"(acc[mt][j][2]), "+f"(acc[mt][j][3])
                        : "r"(A[mt][0]), "r"(A[mt][1]), "r"(A[mt][2]), "r"(A[mt][3]),
                          "r"(B[nt][h]), "r"(B[nt][h + 2]));
                }
            }
        }
        __syncthreads();
        if (tid == 0 && s + STAGES < NKIT) issue(s + STAGES);
    }

    // Epilogue: bias + store (C frag: row=lane/4 (+8), cols=2*(lane%4)+{0,1})
#pragma unroll
    for (int mt = 0; mt < 4; mt++) {
        const int r0 = bm0 + wm + mt * 16 + (lane >> 2);
#pragma unroll
        for (int j = 0; j < 4; j++) {
            const int c0 = bn0 + wn + j * 8 + ((lane & 3) << 1);
            const float2 bb = *(const float2*)(bias + c0);
            float2 v;
            v.x = acc[mt][j][0] + bb.x;
            v.y = acc[mt][j][1] + bb.y;
            *(float2*)(out + (size_t)r0 * OUT_DIM + c0) = v;
            v.x = acc[mt][j][2] + bb.x;
            v.y = acc[mt][j][3] + bb.y;
            *(float2*)(out + (size_t)(r0 + 8) * OUT_DIM + c0) = v;
        }
    }
}

// ---------------------------------------------------------------------------
// Host: build tensormaps (driver entry point via cudart; no libcuda link)
// ---------------------------------------------------------------------------
typedef CUresult (*PFN_encodeTiled)(
    CUtensorMap*, CUtensorMapDataType, cuuint32_t, void*,
    const cuuint64_t*, const cuuint64_t*, const cuuint32_t*, const cuuint32_t*,
    CUtensorMapInterleave, CUtensorMapSwizzle, CUtensorMapL2promotion,
    CUtensorMapFloatOOBfill);

extern "C" void kernel_launch(void* const* d_in, const int* in_sizes, int n_in,
                              void* d_out, int out_size) {
    const float* x    = (const float*)d_in[0];
    const float* lnw  = (const float*)d_in[1];
    const float* lnb  = (const float*)d_in[2];
    const float* sw   = (const float*)d_in[3];
    const float* sb   = (const float*)d_in[4];
    const float* bias = (const float*)d_in[5];
    const float* beta = (const float*)d_in[6];
    const float* grid = (const float*)d_in[7];
    float* out = (float*)d_out;

    void* fn = nullptr;
    cudaDriverEntryPointQueryResult qres;
    cudaGetDriverEntryPoint("cuTensorMapEncodeTiled", &fn, cudaEnableDefault, &qres);
    PFN_encodeTiled encode = (PFN_encodeTiled)fn;

    void *pA = nullptr, *pW = nullptr;
    cudaGetSymbolAddress(&pA, g_A);
    cudaGetSymbolAddress(&pW, g_W);

    CUtensorMap ta, tb;
    {
        cuuint64_t dims[2]    = { (cuuint64_t)KPHYS, (cuuint64_t)BATCH };
        cuuint64_t strides[1] = { (cuuint64_t)KPHYS * 2 };
        cuuint32_t box[2]     = { (cuuint32_t)BK, (cuuint32_t)BM };   // 64 x 128
        cuuint32_t es[2]      = { 1, 1 };
        encode(&ta, CU_TENSOR_MAP_DATA_TYPE_BFLOAT16, 2, pA, dims, strides, box, es,
               CU_TENSOR_MAP_INTERLEAVE_NONE, CU_TENSOR_MAP_SWIZZLE_128B,
               CU_TENSOR_MAP_L2_PROMOTION_L2_128B, CU_TENSOR_MAP_FLOAT_OOB_FILL_NONE);
    }
    {
        cuuint64_t dims[2]    = { (cuuint64_t)KPHYS, (cuuint64_t)OUT_DIM };
        cuuint64_t strides[1] = { (cuuint64_t)KPHYS * 2 };
        cuuint32_t box[2]     = { (cuuint32_t)BK, (cuuint32_t)BN };   // 64 x 128
        cuuint32_t es[2]      = { 1, 1 };
        encode(&tb, CU_TENSOR_MAP_DATA_TYPE_BFLOAT16, 2, pW, dims, strides, box, es,
               CU_TENSOR_MAP_INTERLEAVE_NONE, CU_TENSOR_MAP_SWIZZLE_128B,
               CU_TENSOR_MAP_L2_PROMOTION_L2_128B, CU_TENSOR_MAP_FLOAT_OOB_FILL_NONE);
    }

    cudaFuncSetAttribute(gemm_kernel, cudaFuncAttributeMaxDynamicSharedMemorySize, SM_TOT);

    prep_w_kernel<<<(OUT_DIM * IN_DIM) / 256, 256>>>(sw, sb);
    ln_basis_kernel<<<BATCH, 256>>>(x, lnw, lnb, beta, grid);
    gemm_kernel<<<dim3(OUT_DIM / BN, BATCH / BM), 256, SM_TOT>>>(out, bias, ta, tb);
}